// round 16
// baseline (speedup 1.0000x reference)
#include <cuda_runtime.h>
#include <cstdint>

typedef unsigned int u32;
typedef unsigned short u16;

#define BB 8
#define CC 256
#define CPD 32
#define NN 4096
#define QPW 20   // 80B row pitch in words
#define LOG2E 1.4426950408889634f
#define H2_C14 0x4B004B00u   // fp16x2 (14, 14)

// ======================= helpers =======================
__device__ __forceinline__ u32 smem_to_u32(const void* p) {
    u32 a;
    asm("{ .reg .u64 t; cvta.to.shared.u64 t, %1; cvt.u32.u64 %0, t; }" : "=r"(a) : "l"(p));
    return a;
}
__device__ __forceinline__ void mma_f16(float d[4], const u32 a[4], u32 b0, u32 b1) {
    asm volatile("mma.sync.aligned.m16n8k16.row.col.f32.f16.f16.f32 "
        "{%0,%1,%2,%3},{%4,%5,%6,%7},{%8,%9},{%0,%1,%2,%3};"
        : "+f"(d[0]), "+f"(d[1]), "+f"(d[2]), "+f"(d[3])
        : "r"(a[0]), "r"(a[1]), "r"(a[2]), "r"(a[3]), "r"(b0), "r"(b1));
}
__device__ __forceinline__ void ldsm4(u32 r[4], u32 addr) {
    asm volatile("ldmatrix.sync.aligned.m8n8.x4.shared.b16 {%0,%1,%2,%3},[%4];"
        : "=r"(r[0]), "=r"(r[1]), "=r"(r[2]), "=r"(r[3]) : "r"(addr));
}
__device__ __forceinline__ u16 f2h(float f) {
    u16 r; asm("cvt.rn.f16.f32 %0,%1;" : "=h"(r) : "f"(f)); return r;
}
__device__ __forceinline__ u32 packh(float lo, float hi) {
    u32 r; asm("cvt.rn.f16x2.f32 %0,%1,%2;" : "=r"(r) : "f"(hi), "f"(lo)); return r;
}
__device__ __forceinline__ u32 hmin2(u32 a, u32 b) {
    u32 r; asm("min.f16x2 %0,%1,%2;" : "=r"(r) : "r"(a), "r"(b)); return r;
}
__device__ __forceinline__ u32 hex2(u32 a) {
    u32 r; asm("ex2.approx.f16x2 %0,%1;" : "=r"(r) : "r"(a)); return r;
}
__device__ __forceinline__ float2 h2f2(u32 h) {
    float2 f;
    asm("{.reg .b16 lo,hi;\n\tmov.b32 {lo,hi},%2;\n\tcvt.f32.f16 %0,lo;\n\tcvt.f32.f16 %1,hi;}"
        : "=f"(f.x), "=f"(f.y) : "r"(h));
    return f;
}

// ======================= scratch =======================
__device__ uint4 g_q4[(size_t)BB * NN * 4];          // [b][n] 32 fp16 (pre-scaled by log2e)
__device__ uint4 g_k4[(size_t)BB * NN * 4];          // [b][n] 32 fp16
__device__ float g_vf[(size_t)BB * CPD * NN];        // [b][c][n] f32 (pre-scale)
__device__ uint4 g_vh4[(size_t)BB * CPD * NN / 8];   // [b][c][n] fp16 (post scale_v: v/Z')
__device__ float g_Zp[16][BB * NN];                  // partial Z' sums (deterministic)
__device__ uint4 g_Oph[16][(size_t)BB * NN * 4];     // partial O fp16: [b][i] 16 u32 (word-permuted)

// ======================= proj via MMA: q/k/v =======================
#define PJ_WS 0
#define PJ_AS 50688
#define PJ_BIAS 69120
#define PJ_TOT 69504

__global__ __launch_bounds__(256) void proj_mma_kernel(
    const float* __restrict__ x,
    const float* __restrict__ Wq, const float* __restrict__ bq,
    const float* __restrict__ Wk, const float* __restrict__ bk,
    const float* __restrict__ Wv, const float* __restrict__ bv,
    u32* __restrict__ outq, u32* __restrict__ outk, float* __restrict__ outvf)
{
    extern __shared__ char smp[];
    u32* Ws = (u32*)(smp + PJ_WS);
    u32* As = (u32*)(smp + PJ_AS);
    float* bs = (float*)(smp + PJ_BIAS);
    const u32 sbp = smem_to_u32(smp);
    const int tid = threadIdx.x, w = tid >> 5, lane = tid & 31;
    const int b = blockIdx.y, n0 = blockIdx.x * 128;

    for (int idx = tid; idx < 96 * 128; idx += 256) {
        int row = idx >> 7, c2 = idx & 127;
        const float* src = (row < 32) ? Wq : (row < 64) ? Wk : Wv;
        int o = row & 31;
        Ws[row * 132 + c2] = packh(src[o * 256 + 2 * c2], src[o * 256 + 2 * c2 + 1]);
    }
    if (tid < 96) bs[tid] = (tid < 32) ? bq[tid] : (tid < 64) ? bk[tid - 32] : bv[tid - 64];
    __syncthreads();

    float D[12][4];
#pragma unroll
    for (int ot = 0; ot < 12; ot++) {
        float b0 = bs[ot * 8 + 2 * (lane & 3)];
        float b1 = bs[ot * 8 + 2 * (lane & 3) + 1];
        D[ot][0] = b0; D[ot][1] = b1; D[ot][2] = b0; D[ot][3] = b1;
    }

    for (int kc = 0; kc < 4; kc++) {
        __syncthreads();
        for (int idx = tid; idx < 32 * 128; idx += 256) {
            int c2 = idx >> 7, n = idx & 127;
            const float* xp = x + ((size_t)(b * CC + kc * 64 + 2 * c2)) * NN + n0 + n;
            As[n * 36 + c2] = packh(xp[0], xp[NN]);
        }
        __syncthreads();
        int r = (lane & 7) + ((lane >> 3) & 1) * 8;
        u32 abase = sbp + PJ_AS + (u32)((w * 16 + r) * 144 + (lane >> 4) * 16);
#pragma unroll
        for (int k = 0; k < 4; k++) {
            u32 A[4];
            ldsm4(A, abase + k * 32);
            const int ws = lane & 3;
            const int kb = kc * 32 + k * 8;
#pragma unroll
            for (int ot = 0; ot < 12; ot++) {
                const u32* kr = Ws + (ot * 8 + (lane >> 2)) * 132 + kb;
                mma_f16(D[ot], A, kr[ws], kr[ws + 4]);
            }
        }
    }

    const int nr = w * 16 + (lane >> 2);
#pragma unroll
    for (int ot = 0; ot < 4; ot++) {
        int wd = ot * 4 + (lane & 3);
        outq[((size_t)(b * NN + n0 + nr)) * 16 + wd]     = packh(D[ot][0] * LOG2E, D[ot][1] * LOG2E);
        outq[((size_t)(b * NN + n0 + nr + 8)) * 16 + wd] = packh(D[ot][2] * LOG2E, D[ot][3] * LOG2E);
    }
#pragma unroll
    for (int ot = 4; ot < 8; ot++) {
        int wd = (ot - 4) * 4 + (lane & 3);
        outk[((size_t)(b * NN + n0 + nr)) * 16 + wd]     = packh(D[ot][0], D[ot][1]);
        outk[((size_t)(b * NN + n0 + nr + 8)) * 16 + wd] = packh(D[ot][2], D[ot][3]);
    }
#pragma unroll
    for (int ot = 8; ot < 12; ot++) {
        int c = (ot - 8) * 8 + 2 * (lane & 3);
        float* v0 = outvf + ((size_t)(b * CPD + c)) * NN + n0 + nr;
        float* v1 = outvf + ((size_t)(b * CPD + c + 1)) * NN + n0 + nr;
        v0[0] = D[ot][0]; v1[0] = D[ot][1];
        v0[8] = D[ot][2]; v1[8] = D[ot][3];
    }
}

// ======================= pass 1: Z' partial sums, j-tile 256, i-split 16 =======================
// grid (16 j-tiles, 16 i-splits, 8 b), block 256
__global__ __launch_bounds__(256) void pass1_kernel()
{
    __shared__ __align__(16) u32 Qs[256 * QPW];
    __shared__ __align__(16) u32 Ks[128 * QPW];
    const int tid = threadIdx.x, w = tid >> 5, lane = tid & 31;
    const int b = blockIdx.z, j0 = blockIdx.x * 256, it0 = blockIdx.y * 2;

    for (int idx = tid; idx < 1024; idx += 256) {
        int row = idx >> 2, q = idx & 3;
        uint4 v = g_q4[(size_t)(b * NN + j0 + row) * 4 + q];
        *(uint4*)((char*)Qs + row * 80 + q * 16) = v;
    }
    __syncthreads();

    u32 A[2][2][4];
    {
        int r = (lane & 7) + ((lane >> 3) & 1) * 8;
#pragma unroll
        for (int jf = 0; jf < 2; jf++) {
            u32 base = smem_to_u32(Qs) + (u32)((w * 32 + jf * 16 + r) * 80 + (lane >> 4) * 16);
            ldsm4(A[jf][0], base); ldsm4(A[jf][1], base + 32);
        }
    }

    float z[2][2] = {{0.f, 0.f}, {0.f, 0.f}};
    for (int it = it0; it < it0 + 2; it++) {
        __syncthreads();
        for (int idx = tid; idx < 512; idx += 256) {
            int row = idx >> 2, q = idx & 3;
            uint4 v = g_k4[(size_t)(b * NN + it * 128 + row) * 4 + q];
            *(uint4*)((char*)Ks + row * 80 + q * 16) = v;
        }
        __syncthreads();

#pragma unroll
        for (int nf = 0; nf < 16; nf++) {
            const u32* kr = Ks + (nf * 8 + (lane >> 2)) * QPW;
            const int ws = lane & 3;
            u32 kb0 = kr[ws], kb1 = kr[ws + 4], kb2 = kr[ws + 8], kb3 = kr[ws + 12];
#pragma unroll
            for (int jf = 0; jf < 2; jf++) {
                float d[4] = {-8.f, -8.f, -8.f, -8.f};
                mma_f16(d, A[jf][0], kb0, kb1);
                mma_f16(d, A[jf][1], kb2, kb3);
                u32 e0 = hex2(hmin2(packh(d[0], d[1]), H2_C14));
                u32 e1 = hex2(hmin2(packh(d[2], d[3]), H2_C14));
                float2 f0 = h2f2(e0), f1 = h2f2(e1);
                z[jf][0] += f0.x + f0.y;
                z[jf][1] += f1.x + f1.y;
            }
        }
    }

#pragma unroll
    for (int jf = 0; jf < 2; jf++) {
#pragma unroll
        for (int zr = 0; zr < 2; zr++) {
            z[jf][zr] += __shfl_xor_sync(0xffffffff, z[jf][zr], 1);
            z[jf][zr] += __shfl_xor_sync(0xffffffff, z[jf][zr], 2);
        }
    }
    if ((lane & 3) == 0) {
        int j = j0 + w * 32 + (lane >> 2);
        g_Zp[blockIdx.y][b * NN + j]      = z[0][0];
        g_Zp[blockIdx.y][b * NN + j + 8]  = z[0][1];
        g_Zp[blockIdx.y][b * NN + j + 16] = z[1][0];
        g_Zp[blockIdx.y][b * NN + j + 24] = z[1][1];
    }
}

// ======================= scale_v: V_fp16 = V_f32 / Z' =======================
__global__ __launch_bounds__(256) void scale_v_kernel(u16* __restrict__ vh)
{
    const int n = blockIdx.x * 256 + threadIdx.x;
    const int b = blockIdx.y;
    const int o = b * NN + n;
    float Z = 0.f;
#pragma unroll
    for (int s = 0; s < 16; s++) Z += g_Zp[s][o];
    float iZ = 1.0f / Z;
#pragma unroll 4
    for (int c = 0; c < CPD; c++) {
        size_t off = ((size_t)(b * CPD + c)) * NN + n;
        vh[off] = f2h(g_vf[off] * iZ);
    }
}

// ======================= pass 2: 512 threads, i-tile 256, j-split 16 =======================
// grid (16 i-tiles, 16 j-splits, 8 b), block 512
__global__ __launch_bounds__(512, 2) void pass2_kernel()
{
    __shared__ __align__(16) u32 Ks[256 * QPW];   // 20480 B
    __shared__ __align__(16) u32 Qs[128 * QPW];   // 10240 B
    __shared__ __align__(16) u32 Vs[32 * 68];     // 8704 B
    const int tid = threadIdx.x, w = tid >> 5, lane = tid & 31;
    const int b = blockIdx.z, i0 = blockIdx.x * 256, js = blockIdx.y;

    for (int idx = tid; idx < 1024; idx += 512) {
        int row = idx >> 2, q = idx & 3;
        uint4 v = g_k4[(size_t)(b * NN + i0 + row) * 4 + q];
        *(uint4*)((char*)Ks + row * 80 + q * 16) = v;
    }
    __syncthreads();

    u32 KA[2][4];
    {
        int r = (lane & 7) + ((lane >> 3) & 1) * 8;
        u32 base = smem_to_u32(Ks) + (u32)((w * 16 + r) * 80 + (lane >> 4) * 16);
        ldsm4(KA[0], base); ldsm4(KA[1], base + 32);
    }

    float dO[4][4];
#pragma unroll
    for (int cf = 0; cf < 4; cf++)
#pragma unroll
        for (int r = 0; r < 4; r++) dO[cf][r] = 0.f;

    for (int jt = js * 2; jt < js * 2 + 2; jt++) {
        __syncthreads();
        const int jb = jt * 128;
        {
            int row = tid >> 2, q = tid & 3;
            uint4 v = g_q4[(size_t)(b * NN + jb + row) * 4 + q];
            *(uint4*)((char*)Qs + row * 80 + q * 16) = v;
        }
        {
            int row = tid >> 4, q = tid & 15;
            if (row < 32) {
                uint4 v = g_vh4[(size_t)(b * CPD + row) * (NN / 8) + (jb >> 3) + q];
                *(uint4*)((char*)Vs + row * 272 + q * 16) = v;
            }
        }
        __syncthreads();

#pragma unroll
        for (int jp = 0; jp < 8; jp++) {
            const int ws = lane & 3;
            const u32* qr0 = Qs + (jp * 16 + (lane >> 2)) * QPW;
            const u32* qr1 = Qs + (jp * 16 + 8 + (lane >> 2)) * QPW;
            u32 qb0 = qr0[ws], qb1 = qr0[ws + 4], qb2 = qr0[ws + 8], qb3 = qr0[ws + 12];
            u32 qb4 = qr1[ws], qb5 = qr1[ws + 4], qb6 = qr1[ws + 8], qb7 = qr1[ws + 12];
            float d0[4] = {-8.f, -8.f, -8.f, -8.f};
            float d1[4] = {-8.f, -8.f, -8.f, -8.f};
            mma_f16(d0, KA[0], qb0, qb1);
            mma_f16(d0, KA[1], qb2, qb3);
            mma_f16(d1, KA[0], qb4, qb5);
            mma_f16(d1, KA[1], qb6, qb7);
            u32 aH[4];
            aH[0] = hex2(hmin2(packh(d0[0], d0[1]), H2_C14));
            aH[1] = hex2(hmin2(packh(d0[2], d0[3]), H2_C14));
            aH[2] = hex2(hmin2(packh(d1[0], d1[1]), H2_C14));
            aH[3] = hex2(hmin2(packh(d1[2], d1[3]), H2_C14));
            const int ws2 = jp * 8 + ws;
#pragma unroll
            for (int cf = 0; cf < 4; cf++) {
                const u32* vh = Vs + (cf * 8 + (lane >> 2)) * 68;
                mma_f16(dO[cf], aH, vh[ws2], vh[ws2 + 4]);
            }
        }
    }

    // fragment-direct packed-fp16 partial store (word-permuted: word = ws*4 + cf)
    u32* dstb = (u32*)g_Oph[js];
    {
        int il = w * 16 + (lane >> 2);
        size_t rb = ((size_t)b * NN + i0 + il) * 16 + (lane & 3) * 4;
        *(uint4*)(dstb + rb) = make_uint4(
            packh(dO[0][0], dO[0][1]), packh(dO[1][0], dO[1][1]),
            packh(dO[2][0], dO[2][1]), packh(dO[3][0], dO[3][1]));
        *(uint4*)(dstb + rb + 128) = make_uint4(
            packh(dO[0][2], dO[0][3]), packh(dO[1][2], dO[1][3]),
            packh(dO[2][2], dO[2][3]), packh(dO[3][2], dO[3][3]));
    }
}

// ======================= backproj (fp16 MMA): y = Wb @ sum(O) + bb + x =======================
// grid (32 i-tiles, 8 b), block 256
__global__ __launch_bounds__(256) void backproj_kernel(
    const float* __restrict__ x, const float* __restrict__ Wb,
    const float* __restrict__ bbp, float* __restrict__ y)
{
    __shared__ __align__(16) u32 Osum[128 * QPW];   // 10240 B
    __shared__ __align__(16) u32 Wbh[256 * QPW];    // 20480 B
    __shared__ float bbs[256];
    const int tid = threadIdx.x, w = tid >> 5, lane = tid & 31;
    const int b = blockIdx.y, i0 = blockIdx.x * 128;

    for (int idx = tid; idx < 4096; idx += 256) {
        int c = idx >> 4, wd = idx & 15;
        Wbh[c * QPW + wd] = packh(Wb[c * 32 + 2 * wd], Wb[c * 32 + 2 * wd + 1]);
    }
    if (tid < 256) bbs[tid] = bbp[tid];
    {
        const size_t pofs = ((size_t)b * NN + i0) * 16;
        const u32* p0 = (const u32*)g_Oph[0];
        for (int idx = tid; idx < 2048; idx += 256) {
            int il = idx >> 4, wp = idx & 15;
            size_t a = pofs + il * 16 + wp;
            float2 acc = h2f2(p0[a]);
#pragma unroll
            for (int s = 1; s < 16; s++) {
                float2 t = h2f2(((const u32*)g_Oph[s])[a]);
                acc.x += t.x; acc.y += t.y;
            }
            int natural = (wp & 3) * 4 + (wp >> 2);
            Osum[il * QPW + natural] = packh(acc.x, acc.y);
        }
    }
    __syncthreads();

    u32 A[2][4];
    {
        int r = (lane & 7) + ((lane >> 3) & 1) * 8;
        u32 base = smem_to_u32(Osum) + (u32)((w * 16 + r) * 80 + (lane >> 4) * 16);
        ldsm4(A[0], base); ldsm4(A[1], base + 32);
    }

    const int ws = lane & 3;
    const int ig = i0 + w * 16 + (lane >> 2);
#pragma unroll 4
    for (int cf = 0; cf < 32; cf++) {
        int c0 = cf * 8 + 2 * ws;
        float d[4];
        d[0] = bbs[c0]; d[1] = bbs[c0 + 1]; d[2] = d[0]; d[3] = d[1];
        const u32* kr = Wbh + (cf * 8 + (lane >> 2)) * QPW;
        mma_f16(d, A[0], kr[ws], kr[ws + 4]);
        mma_f16(d, A[1], kr[ws + 8], kr[ws + 12]);
        size_t o0 = ((size_t)(b * CC + c0)) * NN + ig;
        y[o0]          = d[0] + x[o0];
        y[o0 + NN]     = d[1] + x[o0 + NN];
        y[o0 + 8]      = d[2] + x[o0 + 8];
        y[o0 + NN + 8] = d[3] + x[o0 + NN + 8];
    }
}

// ======================= launcher =======================
extern "C" void kernel_launch(void* const* d_in, const int* in_sizes, int n_in,
                              void* d_out, int out_size)
{
    const float* x   = (const float*)d_in[0];
    const float* Wq  = (const float*)d_in[1];
    const float* bq  = (const float*)d_in[2];
    const float* Wk  = (const float*)d_in[3];
    const float* bk  = (const float*)d_in[4];
    const float* Wv  = (const float*)d_in[5];
    const float* bv  = (const float*)d_in[6];
    const float* Wb  = (const float*)d_in[7];
    const float* bbp = (const float*)d_in[8];
    float* y = (float*)d_out;

    uint4 *dq, *dk, *dvh;
    float* dvf;
    cudaGetSymbolAddress((void**)&dq,  g_q4);
    cudaGetSymbolAddress((void**)&dk,  g_k4);
    cudaGetSymbolAddress((void**)&dvf, g_vf);
    cudaGetSymbolAddress((void**)&dvh, g_vh4);

    cudaFuncSetAttribute(proj_mma_kernel, cudaFuncAttributeMaxDynamicSharedMemorySize, PJ_TOT);

    proj_mma_kernel<<<dim3(NN / 128, BB), 256, PJ_TOT>>>(
        x, Wq, bq, Wk, bk, Wv, bv, (u32*)dq, (u32*)dk, dvf);
    pass1_kernel<<<dim3(NN / 256, 16, BB), 256>>>();
    scale_v_kernel<<<dim3(NN / 256, BB), 256>>>((u16*)dvh);
    pass2_kernel<<<dim3(NN / 256, 16, BB), 512>>>();
    backproj_kernel<<<dim3(NN / 128, BB), 256>>>(x, Wb, bbp, y);
}

// round 17
// speedup vs baseline: 1.1348x; 1.1348x over previous
#include <cuda_runtime.h>
#include <cstdint>

typedef unsigned int u32;
typedef unsigned short u16;

#define BB 8
#define CC 256
#define CPD 32
#define NN 4096
#define QPW 20   // 80B row pitch in words
#define LOG2E 1.4426950408889634f
#define H2_C14 0x4B004B00u   // fp16x2 (14, 14)

// ======================= helpers =======================
__device__ __forceinline__ u32 smem_to_u32(const void* p) {
    u32 a;
    asm("{ .reg .u64 t; cvta.to.shared.u64 t, %1; cvt.u32.u64 %0, t; }" : "=r"(a) : "l"(p));
    return a;
}
__device__ __forceinline__ void mma_f16(float d[4], const u32 a[4], u32 b0, u32 b1) {
    asm volatile("mma.sync.aligned.m16n8k16.row.col.f32.f16.f16.f32 "
        "{%0,%1,%2,%3},{%4,%5,%6,%7},{%8,%9},{%0,%1,%2,%3};"
        : "+f"(d[0]), "+f"(d[1]), "+f"(d[2]), "+f"(d[3])
        : "r"(a[0]), "r"(a[1]), "r"(a[2]), "r"(a[3]), "r"(b0), "r"(b1));
}
__device__ __forceinline__ void ldsm4(u32 r[4], u32 addr) {
    asm volatile("ldmatrix.sync.aligned.m8n8.x4.shared.b16 {%0,%1,%2,%3},[%4];"
        : "=r"(r[0]), "=r"(r[1]), "=r"(r[2]), "=r"(r[3]) : "r"(addr));
}
__device__ __forceinline__ u16 f2h(float f) {
    u16 r; asm("cvt.rn.f16.f32 %0,%1;" : "=h"(r) : "f"(f)); return r;
}
__device__ __forceinline__ u32 packh(float lo, float hi) {
    u32 r; asm("cvt.rn.f16x2.f32 %0,%1,%2;" : "=r"(r) : "f"(hi), "f"(lo)); return r;
}
__device__ __forceinline__ u32 hmin2(u32 a, u32 b) {
    u32 r; asm("min.f16x2 %0,%1,%2;" : "=r"(r) : "r"(a), "r"(b)); return r;
}
__device__ __forceinline__ u32 hmul2(u32 a, u32 b) {
    u32 r; asm("mul.f16x2 %0,%1,%2;" : "=r"(r) : "r"(a), "r"(b)); return r;
}
__device__ __forceinline__ u32 hex2(u32 a) {
    u32 r; asm("ex2.approx.f16x2 %0,%1;" : "=r"(r) : "r"(a)); return r;
}
__device__ __forceinline__ float2 h2f2(u32 h) {
    float2 f;
    asm("{.reg .b16 lo,hi;\n\tmov.b32 {lo,hi},%2;\n\tcvt.f32.f16 %0,lo;\n\tcvt.f32.f16 %1,hi;}"
        : "=f"(f.x), "=f"(f.y) : "r"(h));
    return f;
}

// ======================= scratch =======================
__device__ uint4 g_q4[(size_t)BB * NN * 4];          // [b][n] 32 fp16 (pre-scaled by log2e)
__device__ uint4 g_k4[(size_t)BB * NN * 4];          // [b][n] 32 fp16
__device__ uint4 g_vh4[(size_t)BB * CPD * NN / 8];   // [b][c][n] fp16 (UNNORMALIZED)
__device__ float g_Zp[8][BB * NN];                   // partial Z' sums (deterministic)
__device__ u32 g_iZh[BB * NN / 2];                   // packed fp16 (1/Z) pairs
__device__ uint4 g_Oph[8][(size_t)BB * NN * 4];      // partial O fp16: [b][i] 16 u32 (word-permuted)

// ======================= proj via MMA: q/k/v =======================
#define PJ_WS 0
#define PJ_AS 50688
#define PJ_BIAS 69120
#define PJ_TOT 69504

__global__ __launch_bounds__(256) void proj_mma_kernel(
    const float* __restrict__ x,
    const float* __restrict__ Wq, const float* __restrict__ bq,
    const float* __restrict__ Wk, const float* __restrict__ bk,
    const float* __restrict__ Wv, const float* __restrict__ bv,
    u32* __restrict__ outq, u32* __restrict__ outk, u16* __restrict__ outvh)
{
    extern __shared__ char smp[];
    u32* Ws = (u32*)(smp + PJ_WS);
    u32* As = (u32*)(smp + PJ_AS);
    float* bs = (float*)(smp + PJ_BIAS);
    const u32 sbp = smem_to_u32(smp);
    const int tid = threadIdx.x, w = tid >> 5, lane = tid & 31;
    const int b = blockIdx.y, n0 = blockIdx.x * 128;

    for (int idx = tid; idx < 96 * 128; idx += 256) {
        int row = idx >> 7, c2 = idx & 127;
        const float* src = (row < 32) ? Wq : (row < 64) ? Wk : Wv;
        int o = row & 31;
        Ws[row * 132 + c2] = packh(src[o * 256 + 2 * c2], src[o * 256 + 2 * c2 + 1]);
    }
    if (tid < 96) bs[tid] = (tid < 32) ? bq[tid] : (tid < 64) ? bk[tid - 32] : bv[tid - 64];
    __syncthreads();

    float D[12][4];
#pragma unroll
    for (int ot = 0; ot < 12; ot++) {
        float b0 = bs[ot * 8 + 2 * (lane & 3)];
        float b1 = bs[ot * 8 + 2 * (lane & 3) + 1];
        D[ot][0] = b0; D[ot][1] = b1; D[ot][2] = b0; D[ot][3] = b1;
    }

    for (int kc = 0; kc < 4; kc++) {
        __syncthreads();
        for (int idx = tid; idx < 32 * 128; idx += 256) {
            int c2 = idx >> 7, n = idx & 127;
            const float* xp = x + ((size_t)(b * CC + kc * 64 + 2 * c2)) * NN + n0 + n;
            As[n * 36 + c2] = packh(xp[0], xp[NN]);
        }
        __syncthreads();
        int r = (lane & 7) + ((lane >> 3) & 1) * 8;
        u32 abase = sbp + PJ_AS + (u32)((w * 16 + r) * 144 + (lane >> 4) * 16);
#pragma unroll
        for (int k = 0; k < 4; k++) {
            u32 A[4];
            ldsm4(A, abase + k * 32);
            const int ws = lane & 3;
            const int kb = kc * 32 + k * 8;
#pragma unroll
            for (int ot = 0; ot < 12; ot++) {
                const u32* kr = Ws + (ot * 8 + (lane >> 2)) * 132 + kb;
                mma_f16(D[ot], A, kr[ws], kr[ws + 4]);
            }
        }
    }

    const int nr = w * 16 + (lane >> 2);
#pragma unroll
    for (int ot = 0; ot < 4; ot++) {
        int wd = ot * 4 + (lane & 3);
        outq[((size_t)(b * NN + n0 + nr)) * 16 + wd]     = packh(D[ot][0] * LOG2E, D[ot][1] * LOG2E);
        outq[((size_t)(b * NN + n0 + nr + 8)) * 16 + wd] = packh(D[ot][2] * LOG2E, D[ot][3] * LOG2E);
    }
#pragma unroll
    for (int ot = 4; ot < 8; ot++) {
        int wd = (ot - 4) * 4 + (lane & 3);
        outk[((size_t)(b * NN + n0 + nr)) * 16 + wd]     = packh(D[ot][0], D[ot][1]);
        outk[((size_t)(b * NN + n0 + nr + 8)) * 16 + wd] = packh(D[ot][2], D[ot][3]);
    }
#pragma unroll
    for (int ot = 8; ot < 12; ot++) {
        int c = (ot - 8) * 8 + 2 * (lane & 3);
        u16* v0 = outvh + ((size_t)(b * CPD + c)) * NN + n0 + nr;
        u16* v1 = outvh + ((size_t)(b * CPD + c + 1)) * NN + n0 + nr;
        v0[0] = f2h(D[ot][0]); v1[0] = f2h(D[ot][1]);
        v0[8] = f2h(D[ot][2]); v1[8] = f2h(D[ot][3]);
    }
}

// ======================= pass 1: Z' partial sums, j-tile 256 =======================
// grid (16 j-tiles, 8 i-splits, 8 b), block 256
__global__ __launch_bounds__(256) void pass1_kernel()
{
    __shared__ __align__(16) u32 Qs[256 * QPW];
    __shared__ __align__(16) u32 Ks[128 * QPW];
    const int tid = threadIdx.x, w = tid >> 5, lane = tid & 31;
    const int b = blockIdx.z, j0 = blockIdx.x * 256, it0 = blockIdx.y * 4;

    for (int idx = tid; idx < 1024; idx += 256) {
        int row = idx >> 2, q = idx & 3;
        uint4 v = g_q4[(size_t)(b * NN + j0 + row) * 4 + q];
        *(uint4*)((char*)Qs + row * 80 + q * 16) = v;
    }
    __syncthreads();

    u32 A[2][2][4];
    {
        int r = (lane & 7) + ((lane >> 3) & 1) * 8;
#pragma unroll
        for (int jf = 0; jf < 2; jf++) {
            u32 base = smem_to_u32(Qs) + (u32)((w * 32 + jf * 16 + r) * 80 + (lane >> 4) * 16);
            ldsm4(A[jf][0], base); ldsm4(A[jf][1], base + 32);
        }
    }

    float z[2][2] = {{0.f, 0.f}, {0.f, 0.f}};
    for (int it = it0; it < it0 + 4; it++) {
        __syncthreads();
        for (int idx = tid; idx < 512; idx += 256) {
            int row = idx >> 2, q = idx & 3;
            uint4 v = g_k4[(size_t)(b * NN + it * 128 + row) * 4 + q];
            *(uint4*)((char*)Ks + row * 80 + q * 16) = v;
        }
        __syncthreads();

#pragma unroll
        for (int nf = 0; nf < 16; nf++) {
            const u32* kr = Ks + (nf * 8 + (lane >> 2)) * QPW;
            const int ws = lane & 3;
            u32 kb0 = kr[ws], kb1 = kr[ws + 4], kb2 = kr[ws + 8], kb3 = kr[ws + 12];
#pragma unroll
            for (int jf = 0; jf < 2; jf++) {
                float d[4] = {-8.f, -8.f, -8.f, -8.f};
                mma_f16(d, A[jf][0], kb0, kb1);
                mma_f16(d, A[jf][1], kb2, kb3);
                u32 e0 = hex2(hmin2(packh(d[0], d[1]), H2_C14));
                u32 e1 = hex2(hmin2(packh(d[2], d[3]), H2_C14));
                float2 f0 = h2f2(e0), f1 = h2f2(e1);
                z[jf][0] += f0.x + f0.y;
                z[jf][1] += f1.x + f1.y;
            }
        }
    }

#pragma unroll
    for (int jf = 0; jf < 2; jf++) {
#pragma unroll
        for (int zr = 0; zr < 2; zr++) {
            z[jf][zr] += __shfl_xor_sync(0xffffffff, z[jf][zr], 1);
            z[jf][zr] += __shfl_xor_sync(0xffffffff, z[jf][zr], 2);
        }
    }
    if ((lane & 3) == 0) {
        int j = j0 + w * 32 + (lane >> 2);
        g_Zp[blockIdx.y][b * NN + j]      = z[0][0];
        g_Zp[blockIdx.y][b * NN + j + 8]  = z[0][1];
        g_Zp[blockIdx.y][b * NN + j + 16] = z[1][0];
        g_Zp[blockIdx.y][b * NN + j + 24] = z[1][1];
    }
}

// ======================= reduce_z: iZ fp16 pairs =======================
// grid (NN/512, BB), block 256; thread t -> j pair (2t, 2t+1)
__global__ __launch_bounds__(256) void reduce_z_kernel()
{
    const int idx = blockIdx.x * 256 + threadIdx.x;   // pair index
    const int b = blockIdx.y;
    const int j0 = b * NN + idx * 2;
    float Z0 = 0.f, Z1 = 0.f;
#pragma unroll
    for (int s = 0; s < 8; s++) { Z0 += g_Zp[s][j0]; Z1 += g_Zp[s][j0 + 1]; }
    g_iZh[(b * NN) / 2 + idx] = packh(1.0f / Z0, 1.0f / Z1);
}

// ======================= pass 2: 512 threads, i-tile 256, j-split 8, iZ in P =======================
// grid (16 i-tiles, 8 j-splits, 8 b), block 512
__global__ __launch_bounds__(512, 2) void pass2_kernel()
{
    __shared__ __align__(16) u32 Ks[256 * QPW];   // 20480 B
    __shared__ __align__(16) u32 Qs[128 * QPW];   // 10240 B
    __shared__ __align__(16) u32 Vs[32 * 68];     // 8704 B
    __shared__ u32 iZs[64];
    const int tid = threadIdx.x, w = tid >> 5, lane = tid & 31;
    const int b = blockIdx.z, i0 = blockIdx.x * 256, js = blockIdx.y;

    for (int idx = tid; idx < 1024; idx += 512) {
        int row = idx >> 2, q = idx & 3;
        uint4 v = g_k4[(size_t)(b * NN + i0 + row) * 4 + q];
        *(uint4*)((char*)Ks + row * 80 + q * 16) = v;
    }
    __syncthreads();

    u32 KA[2][4];
    {
        int r = (lane & 7) + ((lane >> 3) & 1) * 8;
        u32 base = smem_to_u32(Ks) + (u32)((w * 16 + r) * 80 + (lane >> 4) * 16);
        ldsm4(KA[0], base); ldsm4(KA[1], base + 32);
    }

    float dO[4][4];
#pragma unroll
    for (int cf = 0; cf < 4; cf++)
#pragma unroll
        for (int r = 0; r < 4; r++) dO[cf][r] = 0.f;

    for (int jt = js * 4; jt < js * 4 + 4; jt++) {
        __syncthreads();
        const int jb = jt * 128;
        {
            int row = tid >> 2, q = tid & 3;
            uint4 v = g_q4[(size_t)(b * NN + jb + row) * 4 + q];
            *(uint4*)((char*)Qs + row * 80 + q * 16) = v;
        }
        {
            int row = tid >> 4, q = tid & 15;
            if (row < 32) {
                uint4 v = g_vh4[(size_t)(b * CPD + row) * (NN / 8) + (jb >> 3) + q];
                *(uint4*)((char*)Vs + row * 272 + q * 16) = v;
            }
        }
        if (tid < 64) iZs[tid] = g_iZh[(b * NN + jb) / 2 + tid];
        __syncthreads();

#pragma unroll
        for (int jp = 0; jp < 8; jp++) {
            const int ws = lane & 3;
            const u32* qr0 = Qs + (jp * 16 + (lane >> 2)) * QPW;
            const u32* qr1 = Qs + (jp * 16 + 8 + (lane >> 2)) * QPW;
            u32 qb0 = qr0[ws], qb1 = qr0[ws + 4], qb2 = qr0[ws + 8], qb3 = qr0[ws + 12];
            u32 qb4 = qr1[ws], qb5 = qr1[ws + 4], qb6 = qr1[ws + 8], qb7 = qr1[ws + 12];
            float d0[4] = {-8.f, -8.f, -8.f, -8.f};
            float d1[4] = {-8.f, -8.f, -8.f, -8.f};
            mma_f16(d0, KA[0], qb0, qb1);
            mma_f16(d0, KA[1], qb2, qb3);
            mma_f16(d1, KA[0], qb4, qb5);
            mma_f16(d1, KA[1], qb6, qb7);
            u32 z01 = iZs[jp * 8 + ws];
            u32 z89 = iZs[jp * 8 + 4 + ws];
            u32 aH[4];
            aH[0] = hmul2(hex2(hmin2(packh(d0[0], d0[1]), H2_C14)), z01);
            aH[1] = hmul2(hex2(hmin2(packh(d0[2], d0[3]), H2_C14)), z01);
            aH[2] = hmul2(hex2(hmin2(packh(d1[0], d1[1]), H2_C14)), z89);
            aH[3] = hmul2(hex2(hmin2(packh(d1[2], d1[3]), H2_C14)), z89);
            const int ws2 = jp * 8 + ws;
#pragma unroll
            for (int cf = 0; cf < 4; cf++) {
                const u32* vh = Vs + (cf * 8 + (lane >> 2)) * 68;
                mma_f16(dO[cf], aH, vh[ws2], vh[ws2 + 4]);
            }
        }
    }

    // fragment-direct packed-fp16 partial store (word-permuted: word = ws*4 + cf)
    u32* dstb = (u32*)g_Oph[js];
    {
        int il = w * 16 + (lane >> 2);
        size_t rb = ((size_t)b * NN + i0 + il) * 16 + (lane & 3) * 4;
        *(uint4*)(dstb + rb) = make_uint4(
            packh(dO[0][0], dO[0][1]), packh(dO[1][0], dO[1][1]),
            packh(dO[2][0], dO[2][1]), packh(dO[3][0], dO[3][1]));
        *(uint4*)(dstb + rb + 128) = make_uint4(
            packh(dO[0][2], dO[0][3]), packh(dO[1][2], dO[1][3]),
            packh(dO[2][2], dO[2][3]), packh(dO[3][2], dO[3][3]));
    }
}

// ======================= backproj (fp16 MMA): y = Wb @ sum(O) + bb + x =======================
// grid (32 i-tiles, 8 b), block 256
__global__ __launch_bounds__(256) void backproj_kernel(
    const float* __restrict__ x, const float* __restrict__ Wb,
    const float* __restrict__ bbp, float* __restrict__ y)
{
    __shared__ __align__(16) u32 Osum[128 * QPW];   // 10240 B
    __shared__ __align__(16) u32 Wbh[256 * QPW];    // 20480 B
    __shared__ float bbs[256];
    const int tid = threadIdx.x, w = tid >> 5, lane = tid & 31;
    const int b = blockIdx.y, i0 = blockIdx.x * 128;

    for (int idx = tid; idx < 4096; idx += 256) {
        int c = idx >> 4, wd = idx & 15;
        Wbh[c * QPW + wd] = packh(Wb[c * 32 + 2 * wd], Wb[c * 32 + 2 * wd + 1]);
    }
    if (tid < 256) bbs[tid] = bbp[tid];
    {
        const size_t pofs = ((size_t)b * NN + i0) * 16;
        const u32* p0 = (const u32*)g_Oph[0];
        for (int idx = tid; idx < 2048; idx += 256) {
            int il = idx >> 4, wp = idx & 15;
            size_t a = pofs + il * 16 + wp;
            float2 acc = h2f2(p0[a]);
#pragma unroll
            for (int s = 1; s < 8; s++) {
                float2 t = h2f2(((const u32*)g_Oph[s])[a]);
                acc.x += t.x; acc.y += t.y;
            }
            int natural = (wp & 3) * 4 + (wp >> 2);
            Osum[il * QPW + natural] = packh(acc.x, acc.y);
        }
    }
    __syncthreads();

    u32 A[2][4];
    {
        int r = (lane & 7) + ((lane >> 3) & 1) * 8;
        u32 base = smem_to_u32(Osum) + (u32)((w * 16 + r) * 80 + (lane >> 4) * 16);
        ldsm4(A[0], base); ldsm4(A[1], base + 32);
    }

    const int ws = lane & 3;
    const int ig = i0 + w * 16 + (lane >> 2);
#pragma unroll 4
    for (int cf = 0; cf < 32; cf++) {
        int c0 = cf * 8 + 2 * ws;
        float d[4];
        d[0] = bbs[c0]; d[1] = bbs[c0 + 1]; d[2] = d[0]; d[3] = d[1];
        const u32* kr = Wbh + (cf * 8 + (lane >> 2)) * QPW;
        mma_f16(d, A[0], kr[ws], kr[ws + 4]);
        mma_f16(d, A[1], kr[ws + 8], kr[ws + 12]);
        size_t o0 = ((size_t)(b * CC + c0)) * NN + ig;
        y[o0]          = d[0] + x[o0];
        y[o0 + NN]     = d[1] + x[o0 + NN];
        y[o0 + 8]      = d[2] + x[o0 + 8];
        y[o0 + NN + 8] = d[3] + x[o0 + NN + 8];
    }
}

// ======================= launcher =======================
extern "C" void kernel_launch(void* const* d_in, const int* in_sizes, int n_in,
                              void* d_out, int out_size)
{
    const float* x   = (const float*)d_in[0];
    const float* Wq  = (const float*)d_in[1];
    const float* bq  = (const float*)d_in[2];
    const float* Wk  = (const float*)d_in[3];
    const float* bk  = (const float*)d_in[4];
    const float* Wv  = (const float*)d_in[5];
    const float* bv  = (const float*)d_in[6];
    const float* Wb  = (const float*)d_in[7];
    const float* bbp = (const float*)d_in[8];
    float* y = (float*)d_out;

    uint4 *dq, *dk, *dvh;
    cudaGetSymbolAddress((void**)&dq,  g_q4);
    cudaGetSymbolAddress((void**)&dk,  g_k4);
    cudaGetSymbolAddress((void**)&dvh, g_vh4);

    cudaFuncSetAttribute(proj_mma_kernel, cudaFuncAttributeMaxDynamicSharedMemorySize, PJ_TOT);

    proj_mma_kernel<<<dim3(NN / 128, BB), 256, PJ_TOT>>>(
        x, Wq, bq, Wk, bk, Wv, bv, (u32*)dq, (u32*)dk, (u16*)dvh);
    pass1_kernel<<<dim3(NN / 256, 8, BB), 256>>>();
    reduce_z_kernel<<<dim3(NN / 512, BB), 256>>>();
    pass2_kernel<<<dim3(NN / 256, 8, BB), 512>>>();
    backproj_kernel<<<dim3(NN / 128, BB), 256>>>(x, Wb, bbp, y);
}